// round 12
// baseline (speedup 1.0000x reference)
#include <cuda_runtime.h>

#define N_NODES 100000
#define N_EDGES 1600000
#define H0 256
#define H1 1024
#define IN_DIM 64

// Scratch (no allocations allowed)
__device__ float g_h1[H1];
__device__ float g_x[N_NODES];     // raw relu(FC2) output
__device__ float g_deg[N_NODES];   // degree (incl. self loop)
__device__ float g_dinv[N_NODES];  // deg^-1/2
__device__ float g_xd[N_NODES];    // gcn_w * x[i] * dinv[i]

__device__ __forceinline__ float warp_sum(float s) {
#pragma unroll
    for (int o = 16; o; o >>= 1) s += __shfl_xor_sync(0xffffffffu, s, o);
    return s;
}

// ---------------------------------------------------------------------------
// L1: ALL 391 blocks init a deg slice; blocks 0..127 ALSO compute
// FC0 (redundantly — W0 is L2-resident after the first block) and their
// FC1 slice (warp-per-row).
// ---------------------------------------------------------------------------
__global__ void k1_fc01_deginit(const float* __restrict__ emb,
                                const float* __restrict__ W0,
                                const float* __restrict__ b0,
                                const float* __restrict__ W1,
                                const float* __restrict__ b1) {
    int t = threadIdx.x;
    int gi = blockIdx.x * blockDim.x + t;
    if (gi < N_NODES) g_deg[gi] = 1.0f;

    if (blockIdx.x >= H1 / 8) return;

    __shared__ float se[IN_DIM];
    __shared__ float sh0[H0];
    if (t < IN_DIM) se[t] = emb[t];
    __syncthreads();

    // FC0: one row per thread (blockDim == 256 == H0)
    {
        const float4* w = reinterpret_cast<const float4*>(W0 + (size_t)t * IN_DIM);
        const float4* h = reinterpret_cast<const float4*>(se);
        float s = 0.f;
#pragma unroll
        for (int i = 0; i < IN_DIM / 4; i++) {
            float4 wv = w[i];
            float4 hv = h[i];
            s += wv.x * hv.x + wv.y * hv.y + wv.z * hv.z + wv.w * hv.w;
        }
        sh0[t] = fmaxf(s + b0[t], 0.f);
    }
    __syncthreads();

    // FC1: warp-per-row, 8 rows per block
    int row  = blockIdx.x * 8 + (t >> 5);
    int lane = t & 31;
    const float4* w = reinterpret_cast<const float4*>(W1 + (size_t)row * H0);
    const float4* h = reinterpret_cast<const float4*>(sh0);
    float s = 0.f;
#pragma unroll
    for (int i = lane; i < H0 / 4; i += 32) {
        float4 wv = w[i];
        float4 hv = h[i];
        s += wv.x * hv.x + wv.y * hv.y + wv.z * hv.z + wv.w * hv.w;
    }
    s = warp_sum(s);
    if (lane == 0) g_h1[row] = fmaxf(s + b1[row], 0.f);
}

// ---------------------------------------------------------------------------
// L3 (dominant): FC2 GEMV [1024]->[100000] + ReLU, plus a fused degree-count
// slice (128 edges/block, fire-and-forget REDs riding in the W2 DRAM shadow).
// grid = 12500 blocks (12500*128 = 1.6M edges).
// ---------------------------------------------------------------------------
__global__ void k3_fc2_degcount(const float* __restrict__ W2,
                                const float* __restrict__ b2,
                                const int*   __restrict__ dst) {
    int t = threadIdx.x;

    if (t < 128) {
        int e = blockIdx.x * 128 + t;  // e < 12500*128 == N_EDGES
        atomicAdd(&g_deg[dst[e]], 1.0f);
    }

    __shared__ float sh[H1];
#pragma unroll
    for (int i = t; i < H1; i += 256) sh[i] = g_h1[i];
    __syncthreads();

    int row  = blockIdx.x * 8 + (t >> 5);
    int lane = t & 31;
    if (row >= N_NODES) return;

    const float4* w = reinterpret_cast<const float4*>(W2 + (size_t)row * H1);
    const float4* h = reinterpret_cast<const float4*>(sh);
    float s = 0.f;
#pragma unroll
    for (int i = lane; i < H1 / 4; i += 32) {  // 8 float4 per lane
        float4 wv = __ldcs(&w[i]);             // streaming: read-once weights
        float4 hv = h[i];
        s += wv.x * hv.x + wv.y * hv.y + wv.z * hv.z + wv.w * hv.w;
    }
    s = warp_sum(s);
    if (lane == 0) g_x[row] = fmaxf(s + b2[row], 0.f);
}

// ---------------------------------------------------------------------------
// L3b: node epilogue, float4-vectorized (4 nodes/thread):
//   dinv = rsqrt(deg); xd = gcn_w * x * dinv; out = xd (self-loop term)
// ---------------------------------------------------------------------------
__global__ void k3b_nodeprep(const float* __restrict__ gw,
                             float* __restrict__ out) {
    int i4 = blockIdx.x * blockDim.x + threadIdx.x;
    if (i4 * 4 >= N_NODES) return;  // N_NODES % 4 == 0
    float g = __ldg(gw);
    float4 d = reinterpret_cast<const float4*>(g_deg)[i4];
    float4 x = reinterpret_cast<const float4*>(g_x)[i4];
    float4 di, xd;
    di.x = rsqrtf(d.x); di.y = rsqrtf(d.y);
    di.z = rsqrtf(d.z); di.w = rsqrtf(d.w);
    xd.x = g * x.x * di.x; xd.y = g * x.y * di.y;
    xd.z = g * x.z * di.z; xd.w = g * x.w * di.w;
    reinterpret_cast<float4*>(g_dinv)[i4] = di;
    reinterpret_cast<float4*>(g_xd)[i4]   = xd;
    reinterpret_cast<float4*>(out)[i4]    = xd;
}

// ---------------------------------------------------------------------------
// L4: edge scatter. __launch_bounds__(256,8) caps regs at 32 so 8 blocks/SM
// are resident (2048 thr/SM). Grid-stride, 8 edges/iteration, evict-first
// (__ldcs) index loads so the 12.8MB one-shot stream doesn't displace the
// hot out/xd lines in L2.     out[dst] += g_xd[src]
// ---------------------------------------------------------------------------
#define K4_BLOCKS 1184  // 148 * 8
__global__ void __launch_bounds__(256, 8)
k4_scatter(const int* __restrict__ src,
           const int* __restrict__ dst,
           float* __restrict__ out) {
    const int4* sp = reinterpret_cast<const int4*>(src);
    const int4* dp = reinterpret_cast<const int4*>(dst);
    const int n_pairs = N_EDGES / 8;  // 200000 iterations of 8 edges
    const int stride = K4_BLOCKS * 256;

    for (int g = blockIdx.x * 256 + threadIdx.x; g < n_pairs; g += stride) {
        int4 s0 = __ldcs(&sp[2 * g]);
        int4 s1 = __ldcs(&sp[2 * g + 1]);
        int4 d0 = __ldcs(&dp[2 * g]);
        int4 d1 = __ldcs(&dp[2 * g + 1]);

        float v0 = __ldg(&g_xd[s0.x]);
        float v1 = __ldg(&g_xd[s0.y]);
        float v2 = __ldg(&g_xd[s0.z]);
        float v3 = __ldg(&g_xd[s0.w]);
        float v4 = __ldg(&g_xd[s1.x]);
        float v5 = __ldg(&g_xd[s1.y]);
        float v6 = __ldg(&g_xd[s1.z]);
        float v7 = __ldg(&g_xd[s1.w]);

        atomicAdd(&out[d0.x], v0);
        atomicAdd(&out[d0.y], v1);
        atomicAdd(&out[d0.z], v2);
        atomicAdd(&out[d0.w], v3);
        atomicAdd(&out[d1.x], v4);
        atomicAdd(&out[d1.y], v5);
        atomicAdd(&out[d1.z], v6);
        atomicAdd(&out[d1.w], v7);
    }
}

// ---------------------------------------------------------------------------
// L5: final normalization (float4): out[i] = gcn_b + dinv[i] * out[i]
// ---------------------------------------------------------------------------
__global__ void k5_finalize(float* __restrict__ out,
                            const float* __restrict__ gb) {
    int i4 = blockIdx.x * blockDim.x + threadIdx.x;
    if (i4 * 4 >= N_NODES) return;
    float b = __ldg(gb);
    float4 di = reinterpret_cast<const float4*>(g_dinv)[i4];
    float4 o  = reinterpret_cast<const float4*>(out)[i4];
    o.x = b + di.x * o.x;
    o.y = b + di.y * o.y;
    o.z = b + di.z * o.z;
    o.w = b + di.w * o.w;
    reinterpret_cast<float4*>(out)[i4] = o;
}

// ---------------------------------------------------------------------------
extern "C" void kernel_launch(void* const* d_in, const int* in_sizes, int n_in,
                              void* d_out, int out_size) {
    const float* emb = (const float*)d_in[0];
    const int*   ei  = (const int*)d_in[1];  // [2, E] int32 (JAX x64 off)
    const float* W0  = (const float*)d_in[2];
    const float* b0  = (const float*)d_in[3];
    const float* W1  = (const float*)d_in[4];
    const float* b1  = (const float*)d_in[5];
    const float* W2  = (const float*)d_in[6];
    const float* b2  = (const float*)d_in[7];
    const float* gw  = (const float*)d_in[8];
    const float* gb  = (const float*)d_in[9];
    float*       out = (float*)d_out;

    const int* src = ei;            // row 0
    const int* dst = ei + N_EDGES;  // row 1

    const int NODE_BLOCKS  = (N_NODES + 255) / 256;      // 391
    const int NODE4_BLOCKS = (N_NODES / 4 + 255) / 256;  // 98

    k1_fc01_deginit<<<NODE_BLOCKS, 256>>>(emb, W0, b0, W1, b1);
    k3_fc2_degcount<<<(N_NODES + 7) / 8, 256>>>(W2, b2, dst);
    k3b_nodeprep<<<NODE4_BLOCKS, 256>>>(gw, out);
    k4_scatter<<<K4_BLOCKS, 256>>>(src, dst, out);
    k5_finalize<<<NODE4_BLOCKS, 256>>>(out, gb);
}

// round 13
// speedup vs baseline: 1.0166x; 1.0166x over previous
#include <cuda_runtime.h>

#define N_NODES 100000
#define N_EDGES 1600000
#define H0 256
#define H1 1024
#define IN_DIM 64

// Scratch (no allocations allowed)
__device__ float g_h1[H1];
__device__ float g_x[N_NODES];     // raw relu(FC2) output
__device__ float g_deg[N_NODES];   // degree (incl. self loop)
__device__ float g_dinv[N_NODES];  // deg^-1/2
__device__ float g_xd[N_NODES];    // gcn_w * x[i] * dinv[i]

__device__ __forceinline__ float warp_sum(float s) {
#pragma unroll
    for (int o = 16; o; o >>= 1) s += __shfl_xor_sync(0xffffffffu, s, o);
    return s;
}

// ---------------------------------------------------------------------------
// L1: ALL 391 blocks init a deg slice; blocks 0..127 ALSO compute
// FC0 (redundantly — W0 is L2-resident after the first block) and their
// FC1 slice (warp-per-row).
// ---------------------------------------------------------------------------
__global__ void k1_fc01_deginit(const float* __restrict__ emb,
                                const float* __restrict__ W0,
                                const float* __restrict__ b0,
                                const float* __restrict__ W1,
                                const float* __restrict__ b1) {
    int t = threadIdx.x;
    int gi = blockIdx.x * blockDim.x + t;
    if (gi < N_NODES) g_deg[gi] = 1.0f;

    if (blockIdx.x >= H1 / 8) return;

    __shared__ float se[IN_DIM];
    __shared__ float sh0[H0];
    if (t < IN_DIM) se[t] = emb[t];
    __syncthreads();

    // FC0: one row per thread (blockDim == 256 == H0)
    {
        const float4* w = reinterpret_cast<const float4*>(W0 + (size_t)t * IN_DIM);
        const float4* h = reinterpret_cast<const float4*>(se);
        float s = 0.f;
#pragma unroll
        for (int i = 0; i < IN_DIM / 4; i++) {
            float4 wv = w[i];
            float4 hv = h[i];
            s += wv.x * hv.x + wv.y * hv.y + wv.z * hv.z + wv.w * hv.w;
        }
        sh0[t] = fmaxf(s + b0[t], 0.f);
    }
    __syncthreads();

    // FC1: warp-per-row, 8 rows per block
    int row  = blockIdx.x * 8 + (t >> 5);
    int lane = t & 31;
    const float4* w = reinterpret_cast<const float4*>(W1 + (size_t)row * H0);
    const float4* h = reinterpret_cast<const float4*>(sh0);
    float s = 0.f;
#pragma unroll
    for (int i = lane; i < H0 / 4; i += 32) {
        float4 wv = w[i];
        float4 hv = h[i];
        s += wv.x * hv.x + wv.y * hv.y + wv.z * hv.z + wv.w * hv.w;
    }
    s = warp_sum(s);
    if (lane == 0) g_h1[row] = fmaxf(s + b1[row], 0.f);
}

// ---------------------------------------------------------------------------
// L3 (dominant): FC2 GEMV [1024]->[100000] + ReLU, plus a fused degree-count
// slice (128 edges/block, fire-and-forget REDs riding in the W2 DRAM shadow).
// grid = 12500 blocks (12500*128 = 1.6M edges).
// ---------------------------------------------------------------------------
__global__ void k3_fc2_degcount(const float* __restrict__ W2,
                                const float* __restrict__ b2,
                                const int*   __restrict__ dst) {
    int t = threadIdx.x;

    if (t < 128) {
        int e = blockIdx.x * 128 + t;  // e < 12500*128 == N_EDGES
        atomicAdd(&g_deg[dst[e]], 1.0f);
    }

    __shared__ float sh[H1];
#pragma unroll
    for (int i = t; i < H1; i += 256) sh[i] = g_h1[i];
    __syncthreads();

    int row  = blockIdx.x * 8 + (t >> 5);
    int lane = t & 31;
    if (row >= N_NODES) return;

    const float4* w = reinterpret_cast<const float4*>(W2 + (size_t)row * H1);
    const float4* h = reinterpret_cast<const float4*>(sh);
    float s = 0.f;
#pragma unroll
    for (int i = lane; i < H1 / 4; i += 32) {  // 8 float4 per lane
        float4 wv = __ldcs(&w[i]);             // streaming: read-once weights
        float4 hv = h[i];
        s += wv.x * hv.x + wv.y * hv.y + wv.z * hv.z + wv.w * hv.w;
    }
    s = warp_sum(s);
    if (lane == 0) g_x[row] = fmaxf(s + b2[row], 0.f);
}

// ---------------------------------------------------------------------------
// L3b: node epilogue, float4-vectorized (4 nodes/thread):
//   dinv = rsqrt(deg); xd = gcn_w * x * dinv; out = xd (self-loop term)
// ---------------------------------------------------------------------------
__global__ void k3b_nodeprep(const float* __restrict__ gw,
                             float* __restrict__ out) {
    int i4 = blockIdx.x * blockDim.x + threadIdx.x;
    if (i4 * 4 >= N_NODES) return;  // N_NODES % 4 == 0
    float g = __ldg(gw);
    float4 d = reinterpret_cast<const float4*>(g_deg)[i4];
    float4 x = reinterpret_cast<const float4*>(g_x)[i4];
    float4 di, xd;
    di.x = rsqrtf(d.x); di.y = rsqrtf(d.y);
    di.z = rsqrtf(d.z); di.w = rsqrtf(d.w);
    xd.x = g * x.x * di.x; xd.y = g * x.y * di.y;
    xd.z = g * x.z * di.z; xd.w = g * x.w * di.w;
    reinterpret_cast<float4*>(g_dinv)[i4] = di;
    reinterpret_cast<float4*>(g_xd)[i4]   = xd;
    reinterpret_cast<float4*>(out)[i4]    = xd;
}

// ---------------------------------------------------------------------------
// L4: edge scatter. R9 work distribution (4 edges/thread grid-stride, ALL
// 303k threads busy: 400k groups / 303k threads = 1.32 iters) + reg cap via
// __launch_bounds__(256,8) so 8 blocks/SM are resident (R9 had 6 @ 40 regs).
// Plain index loads (evict-first measurably hurt in R12).
//   out[dst] += g_xd[src]
// ---------------------------------------------------------------------------
#define K4_BLOCKS 1184  // 148 * 8
__global__ void __launch_bounds__(256, 8)
k4_scatter(const int* __restrict__ src,
           const int* __restrict__ dst,
           float* __restrict__ out) {
    const int4* sp = reinterpret_cast<const int4*>(src);
    const int4* dp = reinterpret_cast<const int4*>(dst);
    const int n_groups = N_EDGES / 4;  // 400000
    const int stride = K4_BLOCKS * 256;

    for (int g = blockIdx.x * 256 + threadIdx.x; g < n_groups; g += stride) {
        int4 s4 = sp[g];
        int4 d4 = dp[g];
        float v0 = __ldg(&g_xd[s4.x]);
        float v1 = __ldg(&g_xd[s4.y]);
        float v2 = __ldg(&g_xd[s4.z]);
        float v3 = __ldg(&g_xd[s4.w]);
        atomicAdd(&out[d4.x], v0);
        atomicAdd(&out[d4.y], v1);
        atomicAdd(&out[d4.z], v2);
        atomicAdd(&out[d4.w], v3);
    }
}

// ---------------------------------------------------------------------------
// L5: final normalization (float4): out[i] = gcn_b + dinv[i] * out[i]
// ---------------------------------------------------------------------------
__global__ void k5_finalize(float* __restrict__ out,
                            const float* __restrict__ gb) {
    int i4 = blockIdx.x * blockDim.x + threadIdx.x;
    if (i4 * 4 >= N_NODES) return;
    float b = __ldg(gb);
    float4 di = reinterpret_cast<const float4*>(g_dinv)[i4];
    float4 o  = reinterpret_cast<const float4*>(out)[i4];
    o.x = b + di.x * o.x;
    o.y = b + di.y * o.y;
    o.z = b + di.z * o.z;
    o.w = b + di.w * o.w;
    reinterpret_cast<float4*>(out)[i4] = o;
}

// ---------------------------------------------------------------------------
extern "C" void kernel_launch(void* const* d_in, const int* in_sizes, int n_in,
                              void* d_out, int out_size) {
    const float* emb = (const float*)d_in[0];
    const int*   ei  = (const int*)d_in[1];  // [2, E] int32 (JAX x64 off)
    const float* W0  = (const float*)d_in[2];
    const float* b0  = (const float*)d_in[3];
    const float* W1  = (const float*)d_in[4];
    const float* b1  = (const float*)d_in[5];
    const float* W2  = (const float*)d_in[6];
    const float* b2  = (const float*)d_in[7];
    const float* gw  = (const float*)d_in[8];
    const float* gb  = (const float*)d_in[9];
    float*       out = (float*)d_out;

    const int* src = ei;            // row 0
    const int* dst = ei + N_EDGES;  // row 1

    const int NODE_BLOCKS  = (N_NODES + 255) / 256;      // 391
    const int NODE4_BLOCKS = (N_NODES / 4 + 255) / 256;  // 98

    k1_fc01_deginit<<<NODE_BLOCKS, 256>>>(emb, W0, b0, W1, b1);
    k3_fc2_degcount<<<(N_NODES + 7) / 8, 256>>>(W2, b2, dst);
    k3b_nodeprep<<<NODE4_BLOCKS, 256>>>(gw, out);
    k4_scatter<<<K4_BLOCKS, 256>>>(src, dst, out);
    k5_finalize<<<NODE4_BLOCKS, 256>>>(out, gb);
}

// round 14
// speedup vs baseline: 1.0236x; 1.0069x over previous
#include <cuda_runtime.h>

#define N_NODES 100000
#define N_EDGES 1600000
#define H0 256
#define H1 1024
#define IN_DIM 64

// Scratch (no allocations allowed)
__device__ float g_h1[H1];
__device__ float g_x[N_NODES];     // raw relu(FC2) output
__device__ float g_deg[N_NODES];   // degree (incl. self loop)
__device__ float g_dinv[N_NODES];  // deg^-1/2
__device__ float g_xd[N_NODES];    // gcn_w * x[i] * dinv[i]

__device__ __forceinline__ float warp_sum(float s) {
#pragma unroll
    for (int o = 16; o; o >>= 1) s += __shfl_xor_sync(0xffffffffu, s, o);
    return s;
}

// ---------------------------------------------------------------------------
// L1: single wave of 128 blocks. Every block: float4 deg-init slice
// (25000 float4 over 32768 threads), FC0 (redundant per block, W0 L2-hot),
// then its FC1 slice (warp-per-row, 8 rows/block).
// ---------------------------------------------------------------------------
__global__ void k1_fc01_deginit(const float* __restrict__ emb,
                                const float* __restrict__ W0,
                                const float* __restrict__ b0,
                                const float* __restrict__ W1,
                                const float* __restrict__ b1) {
    int t = threadIdx.x;
    int gi = blockIdx.x * blockDim.x + t;   // 0..32767
    if (gi < N_NODES / 4)
        reinterpret_cast<float4*>(g_deg)[gi] = make_float4(1.f, 1.f, 1.f, 1.f);

    __shared__ float se[IN_DIM];
    __shared__ float sh0[H0];
    if (t < IN_DIM) se[t] = emb[t];
    __syncthreads();

    // FC0: one row per thread (blockDim == 256 == H0)
    {
        const float4* w = reinterpret_cast<const float4*>(W0 + (size_t)t * IN_DIM);
        const float4* h = reinterpret_cast<const float4*>(se);
        float s = 0.f;
#pragma unroll
        for (int i = 0; i < IN_DIM / 4; i++) {
            float4 wv = w[i];
            float4 hv = h[i];
            s += wv.x * hv.x + wv.y * hv.y + wv.z * hv.z + wv.w * hv.w;
        }
        sh0[t] = fmaxf(s + b0[t], 0.f);
    }
    __syncthreads();

    // FC1: warp-per-row, 8 rows per block (128 blocks x 8 = 1024 rows)
    int row  = blockIdx.x * 8 + (t >> 5);
    int lane = t & 31;
    const float4* w = reinterpret_cast<const float4*>(W1 + (size_t)row * H0);
    const float4* h = reinterpret_cast<const float4*>(sh0);
    float s = 0.f;
#pragma unroll
    for (int i = lane; i < H0 / 4; i += 32) {
        float4 wv = w[i];
        float4 hv = h[i];
        s += wv.x * hv.x + wv.y * hv.y + wv.z * hv.z + wv.w * hv.w;
    }
    s = warp_sum(s);
    if (lane == 0) g_h1[row] = fmaxf(s + b1[row], 0.f);
}

// ---------------------------------------------------------------------------
// L3 (dominant): FC2 GEMV [1024]->[100000] + ReLU, plus a fused degree-count
// slice (128 edges/block, fire-and-forget REDs riding in the W2 DRAM shadow).
// h1 is read directly from global (4KB, L1/L2-broadcast-resident): no smem
// staging, no __syncthreads, faster block start across the ~10.5 waves.
// grid = 12500 blocks (12500*128 = 1.6M edges).
// ---------------------------------------------------------------------------
__global__ void k3_fc2_degcount(const float* __restrict__ W2,
                                const float* __restrict__ b2,
                                const int*   __restrict__ dst) {
    int t = threadIdx.x;

    if (t < 128) {
        int e = blockIdx.x * 128 + t;  // e < 12500*128 == N_EDGES
        atomicAdd(&g_deg[dst[e]], 1.0f);
    }

    int row  = blockIdx.x * 8 + (t >> 5);
    int lane = t & 31;
    if (row >= N_NODES) return;

    const float4* w = reinterpret_cast<const float4*>(W2 + (size_t)row * H1);
    const float4* h = reinterpret_cast<const float4*>(g_h1);
    float s = 0.f;
#pragma unroll
    for (int i = lane; i < H1 / 4; i += 32) {  // 8 float4 per lane
        float4 wv = __ldcs(&w[i]);             // streaming: read-once weights
        float4 hv = __ldg(&h[i]);              // L1-resident broadcast
        s += wv.x * hv.x + wv.y * hv.y + wv.z * hv.z + wv.w * hv.w;
    }
    s = warp_sum(s);
    if (lane == 0) g_x[row] = fmaxf(s + b2[row], 0.f);
}

// ---------------------------------------------------------------------------
// L3b: node epilogue, float4-vectorized (4 nodes/thread):
//   dinv = rsqrt(deg); xd = gcn_w * x * dinv; out = xd (self-loop term)
// ---------------------------------------------------------------------------
__global__ void k3b_nodeprep(const float* __restrict__ gw,
                             float* __restrict__ out) {
    int i4 = blockIdx.x * blockDim.x + threadIdx.x;
    if (i4 * 4 >= N_NODES) return;  // N_NODES % 4 == 0
    float g = __ldg(gw);
    float4 d = reinterpret_cast<const float4*>(g_deg)[i4];
    float4 x = reinterpret_cast<const float4*>(g_x)[i4];
    float4 di, xd;
    di.x = rsqrtf(d.x); di.y = rsqrtf(d.y);
    di.z = rsqrtf(d.z); di.w = rsqrtf(d.w);
    xd.x = g * x.x * di.x; xd.y = g * x.y * di.y;
    xd.z = g * x.z * di.z; xd.w = g * x.w * di.w;
    reinterpret_cast<float4*>(g_dinv)[i4] = di;
    reinterpret_cast<float4*>(g_xd)[i4]   = xd;
    reinterpret_cast<float4*>(out)[i4]    = xd;
}

// ---------------------------------------------------------------------------
// L4: edge scatter (structurally floor-bound at ~19-20us; frozen at best
// measured form). 4 edges/thread grid-stride, all 303k threads busy,
// __launch_bounds__(256,8) for 8 resident blocks/SM.
//   out[dst] += g_xd[src]
// ---------------------------------------------------------------------------
#define K4_BLOCKS 1184  // 148 * 8
__global__ void __launch_bounds__(256, 8)
k4_scatter(const int* __restrict__ src,
           const int* __restrict__ dst,
           float* __restrict__ out) {
    const int4* sp = reinterpret_cast<const int4*>(src);
    const int4* dp = reinterpret_cast<const int4*>(dst);
    const int n_groups = N_EDGES / 4;  // 400000
    const int stride = K4_BLOCKS * 256;

    for (int g = blockIdx.x * 256 + threadIdx.x; g < n_groups; g += stride) {
        int4 s4 = sp[g];
        int4 d4 = dp[g];
        float v0 = __ldg(&g_xd[s4.x]);
        float v1 = __ldg(&g_xd[s4.y]);
        float v2 = __ldg(&g_xd[s4.z]);
        float v3 = __ldg(&g_xd[s4.w]);
        atomicAdd(&out[d4.x], v0);
        atomicAdd(&out[d4.y], v1);
        atomicAdd(&out[d4.z], v2);
        atomicAdd(&out[d4.w], v3);
    }
}

// ---------------------------------------------------------------------------
// L5: final normalization (float4): out[i] = gcn_b + dinv[i] * out[i]
// ---------------------------------------------------------------------------
__global__ void k5_finalize(float* __restrict__ out,
                            const float* __restrict__ gb) {
    int i4 = blockIdx.x * blockDim.x + threadIdx.x;
    if (i4 * 4 >= N_NODES) return;
    float b = __ldg(gb);
    float4 di = reinterpret_cast<const float4*>(g_dinv)[i4];
    float4 o  = reinterpret_cast<const float4*>(out)[i4];
    o.x = b + di.x * o.x;
    o.y = b + di.y * o.y;
    o.z = b + di.z * o.z;
    o.w = b + di.w * o.w;
    reinterpret_cast<float4*>(out)[i4] = o;
}

// ---------------------------------------------------------------------------
extern "C" void kernel_launch(void* const* d_in, const int* in_sizes, int n_in,
                              void* d_out, int out_size) {
    const float* emb = (const float*)d_in[0];
    const int*   ei  = (const int*)d_in[1];  // [2, E] int32 (JAX x64 off)
    const float* W0  = (const float*)d_in[2];
    const float* b0  = (const float*)d_in[3];
    const float* W1  = (const float*)d_in[4];
    const float* b1  = (const float*)d_in[5];
    const float* W2  = (const float*)d_in[6];
    const float* b2  = (const float*)d_in[7];
    const float* gw  = (const float*)d_in[8];
    const float* gb  = (const float*)d_in[9];
    float*       out = (float*)d_out;

    const int* src = ei;            // row 0
    const int* dst = ei + N_EDGES;  // row 1

    const int NODE4_BLOCKS = (N_NODES / 4 + 255) / 256;  // 98

    k1_fc01_deginit<<<H1 / 8, 256>>>(emb, W0, b0, W1, b1);   // 128 blocks
    k3_fc2_degcount<<<(N_NODES + 7) / 8, 256>>>(W2, b2, dst);
    k3b_nodeprep<<<NODE4_BLOCKS, 256>>>(gw, out);
    k4_scatter<<<K4_BLOCKS, 256>>>(src, dst, out);
    k5_finalize<<<NODE4_BLOCKS, 256>>>(out, gb);
}